// round 8
// baseline (speedup 1.0000x reference)
#include <cuda_runtime.h>
#include <cuda_bf16.h>
#include <cstdint>

// dist[i,j] = ||s_i||^2 + ||t_j||^2 - 2 <s_i, t_j>
// s: [n, 64] fp32, t: [q, 64] fp32, out: [n, q] fp32. n = q = 16384.
// bf16 mma.m16n8k16 + ldmatrix; cp.async.bulk staging of pre-swizzled tiles;
// two-stage register transpose (quad butterfly + octet gather) so every
// STG.128 writes full 128B lines.

#define D    64
#define BM   128
#define BN   256
#define MAXNQ 16384

__device__ float g_s_sq[MAXNQ];
__device__ float g_t_sq[MAXNQ];
// Pre-swizzled bf16 tiles: within each 128B row, 16B chunk c stored at c^(row&7).
__device__ __nv_bfloat16 g_s_bf[MAXNQ * D];
__device__ __nv_bfloat16 g_t_bf[MAXNQ * D];

// ---------------- prep: fp32 -> pre-swizzled bf16 + row norms ----------------
__global__ void prep_kernel(const float* __restrict__ s,
                            const float* __restrict__ t, int n, int q) {
    const float* src = blockIdx.y ? t : s;
    __nv_bfloat16* dstb = blockIdx.y ? g_t_bf : g_s_bf;
    float* dstn = blockIdx.y ? g_t_sq : g_s_sq;
    const int lim = blockIdx.y ? q : n;
    const int row = blockIdx.x * 64 + (threadIdx.x >> 2);
    const int part = threadIdx.x & 3;
    if (row >= lim) return;
    const float4* p = reinterpret_cast<const float4*>(src + (size_t)row * D) + part * 4;
    float acc = 0.f;
    uint4* rowq = reinterpret_cast<uint4*>(dstb + (size_t)row * D);
    const int sw = row & 7;
#pragma unroll
    for (int j = 0; j < 2; j++) {
        float4 a = p[2 * j], b = p[2 * j + 1];
        acc += a.x * a.x + a.y * a.y + a.z * a.z + a.w * a.w;
        acc += b.x * b.x + b.y * b.y + b.z * b.z + b.w * b.w;
        __nv_bfloat162 h0 = __float22bfloat162_rn(make_float2(a.x, a.y));
        __nv_bfloat162 h1 = __float22bfloat162_rn(make_float2(a.z, a.w));
        __nv_bfloat162 h2 = __float22bfloat162_rn(make_float2(b.x, b.y));
        __nv_bfloat162 h3 = __float22bfloat162_rn(make_float2(b.z, b.w));
        uint4 u;
        u.x = *reinterpret_cast<uint32_t*>(&h0);
        u.y = *reinterpret_cast<uint32_t*>(&h1);
        u.z = *reinterpret_cast<uint32_t*>(&h2);
        u.w = *reinterpret_cast<uint32_t*>(&h3);
        rowq[(part * 2 + j) ^ sw] = u;   // pre-apply ldmatrix swizzle
    }
    acc += __shfl_xor_sync(0xFFFFFFFF, acc, 1);
    acc += __shfl_xor_sync(0xFFFFFFFF, acc, 2);
    if (part == 0) dstn[row] = acc;
}

// ---------------- helpers ----------------
__device__ __forceinline__ void ldsm_x4(uint32_t& r0, uint32_t& r1,
                                        uint32_t& r2, uint32_t& r3,
                                        uint32_t addr) {
    asm volatile("ldmatrix.sync.aligned.m8n8.x4.shared.b16 {%0,%1,%2,%3}, [%4];"
                 : "=r"(r0), "=r"(r1), "=r"(r2), "=r"(r3) : "r"(addr));
}

__device__ __forceinline__ void mma_bf16(float c[4], const uint32_t a[4],
                                         uint32_t b0, uint32_t b1) {
    asm volatile(
        "mma.sync.aligned.m16n8k16.row.col.f32.bf16.bf16.f32 "
        "{%0,%1,%2,%3}, {%4,%5,%6,%7}, {%8,%9}, {%0,%1,%2,%3};"
        : "+f"(c[0]), "+f"(c[1]), "+f"(c[2]), "+f"(c[3])
        : "r"(a[0]), "r"(a[1]), "r"(a[2]), "r"(a[3]), "r"(b0), "r"(b1));
}

__device__ __forceinline__ float2 shfl_xor_f2(float2 v, int m) {
    float2 r;
    r.x = __shfl_xor_sync(0xFFFFFFFFu, v.x, m);
    r.y = __shfl_xor_sync(0xFFFFFFFFu, v.y, m);
    return r;
}

__device__ __forceinline__ float2 shfl_idx_f2(float2 v, int src) {
    float2 r;
    r.x = __shfl_sync(0xFFFFFFFFu, v.x, src);
    r.y = __shfl_sync(0xFFFFFFFFu, v.y, src);
    return r;
}

__device__ __forceinline__ void bulk_cp(uint32_t dst, const void* src,
                                        uint32_t bytes, uint32_t mbar) {
    asm volatile(
        "cp.async.bulk.shared::cluster.global.mbarrier::complete_tx::bytes "
        "[%0], [%1], %2, [%3];"
        :: "r"(dst), "l"(src), "r"(bytes), "r"(mbar) : "memory");
}

// CTA: 128x256 output. 256 threads = 8 warps (2x4); warp tile 64x32 per half.
__global__ __launch_bounds__(256, 2)
void dist_bf16_kernel(float* __restrict__ out, int q) {
    __shared__ __align__(128) __nv_bfloat16 sS[BM * D];   // 16 KB
    __shared__ __align__(128) __nv_bfloat16 sT[BN * D];   // 32 KB
    __shared__ float sSn[BM];
    __shared__ float sTn[BN];
    __shared__ __align__(8) uint64_t mbar;

    const int tid  = threadIdx.x;
    const int lane = tid & 31;
    const int warp = tid >> 5;
    const int wm   = warp >> 2;      // 0..1
    const int wn   = warp & 3;       // 0..3
    const int i4   = lane & 3;       // 0..3

    const int rowBase = blockIdx.y * BM;
    const int colBase = blockIdx.x * BN;

    const uint32_t mb = (uint32_t)__cvta_generic_to_shared(&mbar);
    const uint32_t sS_base = (uint32_t)__cvta_generic_to_shared(sS);
    const uint32_t sT_base = (uint32_t)__cvta_generic_to_shared(sT);

    if (tid == 0)
        asm volatile("mbarrier.init.shared.b64 [%0], 1;" :: "r"(mb) : "memory");
    __syncthreads();

    if (tid == 0) {
        asm volatile("mbarrier.arrive.expect_tx.shared.b64 _, [%0], %1;"
                     :: "r"(mb), "r"((uint32_t)(BM * D * 2 + BN * D * 2)) : "memory");
        bulk_cp(sS_base, g_s_bf + ((size_t)rowBase << 6), BM * D * 2, mb);
        bulk_cp(sT_base, g_t_bf + ((size_t)colBase << 6), BN * D * 2, mb);
    }

    // Norms staged by regular loads while DMA runs.
    if (tid < BM) sSn[tid] = g_s_sq[rowBase + tid];
    sTn[tid] = g_t_sq[colBase + tid];

    // Wait for DMA completion (phase 0).
    {
        uint32_t done;
        asm volatile(
            "{\n\t.reg .pred p;\n\t"
            "mbarrier.try_wait.parity.acquire.cta.shared::cta.b64 p, [%1], 0;\n\t"
            "selp.b32 %0, 1, 0, p;\n\t}"
            : "=r"(done) : "r"(mb) : "memory");
        if (!done) {
            asm volatile(
                "{\n\t.reg .pred P1;\n\t"
                "WL_%=:\n\t"
                "mbarrier.try_wait.parity.acquire.cta.shared::cta.b64 P1, [%0], 0, 0x989680;\n\t"
                "@P1 bra.uni WD_%=;\n\tbra.uni WL_%=;\n\tWD_%=:\n\t}"
                :: "r"(mb) : "memory");
        }
    }
    __syncthreads();

    const int mrow = wm * 64;
    const int aRow  = mrow + (lane & 15);                 // + mb*16
    const int aXor  = lane & 7;
    const int kAdd  = lane >> 4;                          // chunk +0/+1
    const int bRowL = (lane & 7) + ((lane >> 3) & 1) * 8; // + nk*16 + ncol

    // Octet-gather constants (epilogue).
    const int gSrcLo = lane >> 1;          // source lane for s=0 (s=1: +16)
    const int oddL   = lane & 1;
    const int rOff   = lane >> 3;          // 0..3 row within store group
    const int cOff   = 4 * (lane & 7);     // float col within 32-col span

#pragma unroll 1
    for (int nb = 0; nb < 2; nb++) {
        const int ncol = nb * 128 + wn * 32;

        float acc[4][4][4];
#pragma unroll
        for (int a = 0; a < 4; a++)
#pragma unroll
            for (int b = 0; b < 4; b++)
#pragma unroll
                for (int c = 0; c < 4; c++) acc[a][b][c] = 0.f;

#pragma unroll
        for (int ks = 0; ks < 4; ks++) {       // K = 4 * 16
            const int k2 = ks * 2;
            uint32_t a[4][4];
#pragma unroll
            for (int mb2 = 0; mb2 < 4; mb2++) {
                const int row = aRow + mb2 * 16;
                const uint32_t addr =
                    sS_base + (uint32_t)(row * 8 + ((k2 + kAdd) ^ aXor)) * 16;
                ldsm_x4(a[mb2][0], a[mb2][1], a[mb2][2], a[mb2][3], addr);
            }
            uint32_t b[2][4];
#pragma unroll
            for (int nk = 0; nk < 2; nk++) {
                const int trow = ncol + nk * 16 + bRowL;
                const uint32_t addr =
                    sT_base + (uint32_t)(trow * 8 + ((k2 + kAdd) ^ (trow & 7))) * 16;
                ldsm_x4(b[nk][0], b[nk][1], b[nk][2], b[nk][3], addr);
            }
#pragma unroll
            for (int mb2 = 0; mb2 < 4; mb2++)
#pragma unroll
                for (int nk = 0; nk < 2; nk++) {
                    mma_bf16(acc[mb2][nk * 2 + 0], a[mb2], b[nk][0], b[nk][2]);
                    mma_bf16(acc[mb2][nk * 2 + 1], a[mb2], b[nk][1], b[nk][2 + 1]);
                }
        }

        // ---- Epilogue: quad butterfly + octet gather -> full-line STG.128 ----
        // After butterfly: lane (g,i4) holds (tsq - 2*cross) for row g (+8h),
        // cols [8*i4, 8*i4+8). Octet gather: dest lane L takes float4 from
        // source S = 16*s + (L>>1), half chosen by L&1 -> lane L holds row
        // 4*s + (L>>3), cols [4*(L&7), +4). One STG.128 covers 4 full lines.
        const float4 tn0 = *reinterpret_cast<const float4*>(&sTn[ncol + 8 * i4]);
        const float4 tn1 = *reinterpret_cast<const float4*>(&sTn[ncol + 8 * i4 + 4]);

#pragma unroll
        for (int mb2 = 0; mb2 < 4; mb2++) {
#pragma unroll
            for (int h = 0; h < 2; h++) {
                float2 pv[4];
#pragma unroll
                for (int nf = 0; nf < 4; nf++)
                    pv[nf] = make_float2(acc[mb2][nf][2 * h], acc[mb2][nf][2 * h + 1]);

                // stage 1: quad butterfly (xor 1 then xor 2)
                {
                    float2 t0 = shfl_xor_f2(pv[1], 1);
                    float2 t1 = shfl_xor_f2(pv[0], 1);
                    float2 t2 = shfl_xor_f2(pv[3], 1);
                    float2 t3 = shfl_xor_f2(pv[2], 1);
                    if (i4 & 1) { pv[0] = t0; pv[2] = t2; }
                    else        { pv[1] = t1; pv[3] = t3; }
                }
                {
                    float2 u0 = shfl_xor_f2(pv[2], 2);
                    float2 u1 = shfl_xor_f2(pv[3], 2);
                    float2 u2 = shfl_xor_f2(pv[0], 2);
                    float2 u3 = shfl_xor_f2(pv[1], 2);
                    if (i4 & 2) { pv[0] = u0; pv[1] = u1; }
                    else        { pv[2] = u2; pv[3] = u3; }
                }

                // fold in tsq - 2*cross (col-dependent -> travels with value)
                pv[0].x = fmaf(-2.f, pv[0].x, tn0.x);
                pv[0].y = fmaf(-2.f, pv[0].y, tn0.y);
                pv[1].x = fmaf(-2.f, pv[1].x, tn0.z);
                pv[1].y = fmaf(-2.f, pv[1].y, tn0.w);
                pv[2].x = fmaf(-2.f, pv[2].x, tn1.x);
                pv[2].y = fmaf(-2.f, pv[2].y, tn1.y);
                pv[3].x = fmaf(-2.f, pv[3].x, tn1.z);
                pv[3].y = fmaf(-2.f, pv[3].y, tn1.w);

                // stage 2: octet gather + store, s = 0,1
#pragma unroll
                for (int sgrp = 0; sgrp < 2; sgrp++) {
                    const int S = sgrp * 16 + gSrcLo;
                    float2 a0 = shfl_idx_f2(pv[0], S);
                    float2 a1 = shfl_idx_f2(pv[1], S);
                    float2 a2 = shfl_idx_f2(pv[2], S);
                    float2 a3 = shfl_idx_f2(pv[3], S);
                    float2 lo = oddL ? a2 : a0;
                    float2 hi = oddL ? a3 : a1;

                    const int r = mrow + mb2 * 16 + 8 * h + 4 * sgrp + rOff;
                    const float srow = sSn[r];
                    float4 v;
                    v.x = srow + lo.x;
                    v.y = srow + lo.y;
                    v.z = srow + hi.x;
                    v.w = srow + hi.y;
                    *reinterpret_cast<float4*>(
                        out + (size_t)(rowBase + r) * q + colBase + ncol + cOff) = v;
                }
            }
        }
    }
}

extern "C" void kernel_launch(void* const* d_in, const int* in_sizes, int n_in,
                              void* d_out, int out_size) {
    const float* s = (const float*)d_in[0];
    const float* t = (const float*)d_in[1];
    float* out = (float*)d_out;

    const int n = in_sizes[0] / D;
    const int q = in_sizes[1] / D;

    dim3 pgrid((((n > q) ? n : q) + 63) / 64, 2);
    prep_kernel<<<pgrid, 256>>>(s, t, n, q);

    dim3 grid(q / BN, n / BM);
    dist_bf16_kernel<<<grid, 256>>>(out, q);
}